// round 10
// baseline (speedup 1.0000x reference)
#include <cuda_runtime.h>

// TSModel 2-layer LSTM (layer0: 1->64; layer1: 64->1 fed c0; out = c1/step).
// B=2048 rows, T=1024 steps.
//
// R9 = R8 + (a) 4 independent FFMA2 accumulator chains in P1 (hides lat-4),
//          (b) layer-1 distributed across 8 warps (warp w -> row w) instead
//              of a serial tail on warp 0.
// 296 CTAs x 256 threads (2 CTAs/SM, 7 rows/CTA = 14 rows/SM balanced).
// Warp (q=wid>>1, kh=wid&1): gate-type q, K-half kh; lane l owns gate pair
// (64q+2l, +1) with K-slice weights in 32 ull regs; h via LDS.128 broadcast.

#define UNITS   64
#define TSTEPS  1024
#define ROWS    7
#define NCTA    296
#define NT      256
#define NROWS_TOTAL 2048

typedef unsigned long long ull;

__device__ __forceinline__ ull ffma2(ull a, ull b, ull c) {
    ull d;
    asm("fma.rn.f32x2 %0, %1, %2, %3;" : "=l"(d) : "l"(a), "l"(b), "l"(c));
    return d;
}
__device__ __forceinline__ ull addf2(ull a, ull b) {
    ull d;
    asm("add.rn.f32x2 %0, %1, %2;" : "=l"(d) : "l"(a), "l"(b));
    return d;
}
__device__ __forceinline__ ull pack2(float x, float y) {
    ull d;
    asm("mov.b64 %0, {%1, %2};" : "=l"(d) : "f"(x), "f"(y));
    return d;
}
__device__ __forceinline__ float2 unpack2(ull v) {
    float2 f;
    asm("mov.b64 {%0, %1}, %2;" : "=f"(f.x), "=f"(f.y) : "l"(v));
    return f;
}
__device__ __forceinline__ float sigf(float x) {
    return __fdividef(1.0f, 1.0f + __expf(-x));
}
__device__ __forceinline__ float tanhfast(float x) {
    return 2.0f * __fdividef(1.0f, 1.0f + __expf(-2.0f * x)) - 1.0f;
}

__global__ void __launch_bounds__(NT, 2)
lstm_kernel(const float* __restrict__ input,
            const float* __restrict__ W_ih0, const float* __restrict__ W_hh0,
            const float* __restrict__ b_ih0, const float* __restrict__ b_hh0,
            const float* __restrict__ W_ih1, const float* __restrict__ W_hh1,
            const float* __restrict__ b_ih1, const float* __restrict__ b_hh1,
            float* __restrict__ out)
{
    __shared__ __align__(16) float gbuf[ROWS][2][4][UNITS]; // K-half partials
    __shared__ __align__(16) float hbuf[ROWS][UNITS];       // h0 state
    __shared__ __align__(16) float cbuf[ROWS][68];          // c0_new (padded)
    __shared__ __align__(16) float xtile[ROWS][64];         // staged input
    __shared__ __align__(16) float W1s[4][68];              // W_ih1

    const int row0 = blockIdx.x * ROWS;
    if (row0 >= NROWS_TOTAL) return;    // fully-OOB CTAs exit

    const int tid  = threadIdx.x;
    const int wid  = tid >> 5;
    const int lane = tid & 31;
    const int q    = wid >> 1;          // gate type (i,f,g,o)
    const int kh   = wid & 1;           // K-half

    // ---- one-time init ----
    const int gA = 64 * q + 2 * lane;   // lane's f32x2-adjacent gate pair
    const int gB = gA + 1;
    ull wregA[16], wregB[16];           // weights for K-slice [32kh,32kh+32)
    {
        const ulonglong2* wa = (const ulonglong2*)(W_hh0 + gA * UNITS + 32 * kh);
        const ulonglong2* wb = (const ulonglong2*)(W_hh0 + gB * UNITS + 32 * kh);
#pragma unroll
        for (int m = 0; m < 8; m++) {
            ulonglong2 va = wa[m], vb = wb[m];
            wregA[2 * m] = va.x; wregA[2 * m + 1] = va.y;
            wregB[2 * m] = vb.x; wregB[2 * m + 1] = vb.y;
        }
    }
    // x/bias injected only by the kh==0 warp (halves summed in P2)
    const float wihA = (kh == 0) ? W_ih0[gA] : 0.0f;
    const float wihB = (kh == 0) ? W_ih0[gB] : 0.0f;
    const float bsA  = (kh == 0) ? (b_ih0[gA] + b_hh0[gA]) : 0.0f;
    const float bsB  = (kh == 0) ? (b_ih0[gB] + b_hh0[gB]) : 0.0f;

    if (tid < 4 * UNITS) W1s[tid >> 6][tid & 63] = W_ih1[tid];
    {
        float* hb = &hbuf[0][0];
        for (int i = tid; i < ROWS * UNITS; i += NT) hb[i] = 0.0f;
    }

    // P2 identity: unit u2, rows {rs, rs+4} (second row only for rs<3)
    const int u2 = tid & 63;
    const int rs = tid >> 6;            // 0..3
    float c0s[2] = {0.f, 0.f};

    // layer-1 identity: warp wid owns row wid (wid<7). Lane: gate lq = lane>>3,
    // sub-slice ls = lane&7 (8 c-elements). h1/c1 replicated across the warp.
    const int lq = lane >> 3;
    const int ls = lane & 7;
    const float wh1 = W_hh1[lq];
    const float b1  = b_ih1[lq] + b_hh1[lq];
    float h1s = 0.f, c1s = 0.f;

    __syncthreads();

    for (int t = 0; t < TSTEPS; t++) {
        const int tm = t & 63;
        if (tm == 0) {
            // stage 64 timesteps for the CTA's rows (coalesced; clamp OOB)
#pragma unroll
            for (int i = 0; i < 2; i++) {
                int lin = tid + NT * i;
                if (lin < ROWS * 64) {
                    int rr = lin >> 6, cc = lin & 63;
                    int grow = row0 + rr;
                    if (grow > NROWS_TOTAL - 1) grow = NROWS_TOTAL - 1;
                    xtile[rr][cc] = input[grow * TSTEPS + t + cc];
                }
            }
            __syncthreads();
        }

        // ---- P1: 2 gates x 7 rows over this K-half; 4 indep FFMA2 chains ----
#pragma unroll
        for (int r = 0; r < ROWS; r++) {
            const ulonglong2* hv = (const ulonglong2*)(hbuf[r] + 32 * kh);
            float xv = xtile[r][tm];
            ull accA0 = pack2(fmaf(xv, wihA, bsA), 0.0f);
            ull accB0 = pack2(fmaf(xv, wihB, bsB), 0.0f);
            ull accA1 = 0ULL, accB1 = 0ULL;
#pragma unroll
            for (int m = 0; m < 8; m++) {        // 8 x 16B = this K-half
                ulonglong2 h2 = hv[m];
                accA0 = ffma2(h2.x, wregA[2 * m],     accA0);
                accB0 = ffma2(h2.x, wregB[2 * m],     accB0);
                accA1 = ffma2(h2.y, wregA[2 * m + 1], accA1);
                accB1 = ffma2(h2.y, wregB[2 * m + 1], accB1);
            }
            float2 fa = unpack2(addf2(accA0, accA1));
            float2 fb = unpack2(addf2(accB0, accB1));
            *(ull*)&gbuf[r][kh][q][2 * lane] = pack2(fa.x + fa.y, fb.x + fb.y);
        }
        __syncthreads();   // S1: partials ready

        // ---- P2: combine K-halves + layer-0 cell update ----
#pragma unroll
        for (int j = 0; j < 2; j++) {
            const int r = rs + 4 * j;
            if (j == 1 && rs >= ROWS - 4) break;   // rows 4..6 only
            float iv = sigf(gbuf[r][0][0][u2] + gbuf[r][1][0][u2]);
            float fv = sigf(gbuf[r][0][1][u2] + gbuf[r][1][1][u2]);
            float gv = tanhfast(gbuf[r][0][2][u2] + gbuf[r][1][2][u2]);
            float ov = sigf(gbuf[r][0][3][u2] + gbuf[r][1][3][u2]);
            float c  = fmaf(fv, c0s[j], iv * gv);
            c0s[j] = c;
            hbuf[r][u2] = ov * tanhfast(c);
            cbuf[r][u2] = c;   // layer-1 input is the CELL state (ref quirk)
        }
        __syncthreads();   // S2: h, c0_new ready

        // ---- layer 1: warp wid -> row wid; ~60 cyc, all warps parallel ----
        if (wid < ROWS) {
            const ulonglong2* cv = (const ulonglong2*)(cbuf[wid] + 8 * ls);
            const ulonglong2* wv = (const ulonglong2*)(W1s[lq] + 8 * ls);
            ull pa = 0ULL, pb = 0ULL;
#pragma unroll
            for (int m = 0; m < 2; m++) {        // 8 elems of the 64-dot
                ulonglong2 c2 = cv[m], w2 = wv[m];
                pa = ffma2(c2.x, w2.x, pa);
                pb = ffma2(c2.y, w2.y, pb);
            }
            float2 fa = unpack2(pa), fb = unpack2(pb);
            float p = (fa.x + fb.x) + (fa.y + fb.y);
            p += __shfl_xor_sync(0xffffffffu, p, 1);
            p += __shfl_xor_sync(0xffffffffu, p, 2);
            p += __shfl_xor_sync(0xffffffffu, p, 4);   // 8-lane group sum

            float pre = p + b1 + wh1 * h1s;
            float act = (lq == 2) ? tanhfast(pre) : sigf(pre);
            // gather all 4 gates into every lane
            float t8  = __shfl_xor_sync(0xffffffffu, act, 8);   // gate lq^1
            float t16 = __shfl_xor_sync(0xffffffffu, act, 16);  // gate lq^2
            float t24 = __shfl_xor_sync(0xffffffffu, t8, 16);   // gate lq^3
            float i1 = (lq == 0) ? act : (lq == 1) ? t8 : (lq == 2) ? t16 : t24;
            float f1 = (lq == 1) ? act : (lq == 0) ? t8 : (lq == 3) ? t16 : t24;
            float g1 = (lq == 2) ? act : (lq == 3) ? t8 : (lq == 0) ? t16 : t24;
            float o1 = (lq == 3) ? act : (lq == 2) ? t8 : (lq == 1) ? t16 : t24;

            float c1n = fmaf(f1, c1s, i1 * g1);
            c1s = c1n;                     // replicated identically in all lanes
            h1s = o1 * tanhfast(c1n);
            if (lane == 0 && (row0 + wid) < NROWS_TOTAL)
                out[(row0 + wid) * TSTEPS + t] = c1n;
        }
    }
}

extern "C" void kernel_launch(void* const* d_in, const int* in_sizes, int n_in,
                              void* d_out, int out_size) {
    const float* input = (const float*)d_in[0];
    const float* W_ih0 = (const float*)d_in[1];
    const float* W_hh0 = (const float*)d_in[2];
    const float* b_ih0 = (const float*)d_in[3];
    const float* b_hh0 = (const float*)d_in[4];
    const float* W_ih1 = (const float*)d_in[5];
    const float* W_hh1 = (const float*)d_in[6];
    const float* b_ih1 = (const float*)d_in[7];
    const float* b_hh1 = (const float*)d_in[8];
    float* out = (float*)d_out;

    lstm_kernel<<<NCTA, NT>>>(
        input, W_ih0, W_hh0, b_ih0, b_hh0, W_ih1, W_hh1, b_ih1, b_hh1, out);
}